// round 14
// baseline (speedup 1.0000x reference)
#include <cuda_runtime.h>
#include <cuda_fp16.h>
#include <math.h>

#define B_    8
#define L_    4106
#define C_    768
#define VPT   10
#define NH    12
#define HD    64
#define WS    14
#define NWIN  25
#define BW    200
#define LW    206
#define BH    2400
#define MX    32848        // B_*L_
#define MQ    41200        // BW*LW
#define APITCH 208
#define ASLAB  (APITCH*APITCH)

// ---------------- scratch (static, allocation-free) ----------------
__device__ float  g_xn [25227264];    // half: LN1 out / LN2 out
__device__ float  g_tok[31641600];    // half: tok; later attn@v (half)
__device__ float  g_qkv[94924800];    // half: qkv
__device__ float  g_attn[103850000];  // fp32 attn scores (S+rel); later half MLP hidden
__device__ float  g_proj[31641600];   // fp32 proj out
__device__ float  g_x2 [25227264];    // fp32 residual
__device__ float  g_w  [7077888];     // half: converted weights qkv|proj|w1|w2
__device__ __half g_p  [103900000];   // half: softmax P

#define WOFF_QKV  0
#define WOFF_PROJ 1769472
#define WOFF_W1   2359296
#define WOFF_W2   4718592
#define N_WTOT    7077888

#define CPA16(dst_u32, src_ptr, pred) \
    asm volatile("cp.async.cg.shared.global [%0], [%1], 16, %2;" \
                 :: "r"(dst_u32), "l"(src_ptr), "r"((pred) ? 16 : 0))
#define CP_COMMIT() asm volatile("cp.async.commit_group;")

#define MMA_F16(d, a, b) \
    asm volatile("mma.sync.aligned.m16n8k16.row.col.f32.f16.f16.f32 " \
        "{%0,%1,%2,%3},{%4,%5,%6,%7},{%8,%9},{%0,%1,%2,%3};" \
        : "+f"(d[0]), "+f"(d[1]), "+f"(d[2]), "+f"(d[3]) \
        : "r"(a[0]), "r"(a[1]), "r"(a[2]), "r"(a[3]), "r"(b[0]), "r"(b[1]))

#define LDM_X4(r0, r1, r2, r3, addr) \
    asm volatile("ldmatrix.sync.aligned.m8n8.x4.shared.b16 {%0,%1,%2,%3},[%4];" \
        : "=r"(r0), "=r"(r1), "=r"(r2), "=r"(r3) : "r"(addr))

// ---------------- all-weights convert fp32 -> fp16 (single launch) ----------------
__global__ void convert_w_all(const float* __restrict__ qkv_w,
        const float* __restrict__ proj_w, const float* __restrict__ w1,
        const float* __restrict__ w2, __half* __restrict__ out)
{
    int i = blockIdx.x * 256 + threadIdx.x;
    if (i >= N_WTOT) return;
    float v;
    if (i < WOFF_PROJ)      v = qkv_w[i];
    else if (i < WOFF_W1)   v = proj_w[i - WOFF_PROJ];
    else if (i < WOFF_W2)   v = w1[i - WOFF_W1];
    else                    v = w2[i - WOFF_W2];
    out[i] = __float2half_rn(v);
}

// ---------------- LayerNorm, half out ----------------
__global__ void __launch_bounds__(256) ln_kernel(const float* __restrict__ x,
        const float* __restrict__ w, const float* __restrict__ b,
        __half* __restrict__ out)
{
    int row = blockIdx.x, t = threadIdx.x;
    const float* xr = x + (size_t)row * C_;
    float v0 = xr[t], v1 = xr[t + 256], v2 = xr[t + 512];
    float s  = v0 + v1 + v2;
    float s2 = v0 * v0 + v1 * v1 + v2 * v2;
    __shared__ float r1[8], r2[8];
    #pragma unroll
    for (int o = 16; o > 0; o >>= 1) {
        s  += __shfl_xor_sync(0xffffffffu, s,  o);
        s2 += __shfl_xor_sync(0xffffffffu, s2, o);
    }
    if ((t & 31) == 0) { r1[t >> 5] = s; r2[t >> 5] = s2; }
    __syncthreads();
    float S = 0.f, S2 = 0.f;
    #pragma unroll
    for (int wi = 0; wi < 8; wi++) { S += r1[wi]; S2 += r2[wi]; }
    float mean = S * (1.f / C_);
    float var  = S2 * (1.f / C_) - mean * mean;
    float rstd = rsqrtf(var + 1e-5f);
    __half* orow = out + (size_t)row * C_;
    orow[t]       = __float2half_rn((v0 - mean) * rstd * w[t]       + b[t]);
    orow[t + 256] = __float2half_rn((v1 - mean) * rstd * w[t + 256] + b[t + 256]);
    orow[t + 512] = __float2half_rn((v2 - mean) * rstd * w[t + 512] + b[t + 512]);
}

// ---------------- fused un-window + prompt-mean + residual + LN2 ----------------
__global__ void __launch_bounds__(256) combine_ln(const float* __restrict__ x,
        const float* __restrict__ proj, const float* __restrict__ w,
        const float* __restrict__ b, float* __restrict__ x2,
        __half* __restrict__ xn)
{
    int row = blockIdx.x, t = threadIdx.x;
    int bb = row / L_, tt = row % L_;
    const float* psrc = nullptr;
    bool prompt = (tt < VPT);
    if (!prompt) {
        int sp = tt - VPT;
        int h = sp >> 6, wc = sp & 63;
        int wh = h / WS,  i2 = h % WS;
        int ww = wc / WS, j2 = wc % WS;
        int bw = bb * NWIN + wh * 5 + ww;
        int l  = VPT + i2 * WS + j2;
        psrc = proj + ((size_t)bw * LW + l) * C_;
    }
    float v[3];
    #pragma unroll
    for (int j = 0; j < 3; j++) {
        int c = t + j * 256;
        float val;
        if (prompt) {
            float s = 0.f;
            #pragma unroll
            for (int w2 = 0; w2 < NWIN; w2++)
                s += proj[((size_t)(w2 * B_ + bb) * LW + tt) * C_ + c];
            val = s * (1.f / NWIN);
        } else {
            val = psrc[c];
        }
        v[j] = x[(size_t)row * C_ + c] + val;
        x2[(size_t)row * C_ + c] = v[j];
    }
    float s  = v[0] + v[1] + v[2];
    float s2 = v[0] * v[0] + v[1] * v[1] + v[2] * v[2];
    __shared__ float r1[8], r2[8];
    #pragma unroll
    for (int o = 16; o > 0; o >>= 1) {
        s  += __shfl_xor_sync(0xffffffffu, s,  o);
        s2 += __shfl_xor_sync(0xffffffffu, s2, o);
    }
    if ((t & 31) == 0) { r1[t >> 5] = s; r2[t >> 5] = s2; }
    __syncthreads();
    float S = 0.f, S2 = 0.f;
    #pragma unroll
    for (int wi = 0; wi < 8; wi++) { S += r1[wi]; S2 += r2[wi]; }
    float mean = S * (1.f / C_);
    float var  = S2 * (1.f / C_) - mean * mean;
    float rstd = rsqrtf(var + 1e-5f);
    __half* orow = xn + (size_t)row * C_;
    #pragma unroll
    for (int j = 0; j < 3; j++) {
        int c = t + j * 256;
        orow[c] = __float2half_rn((v[j] - mean) * rstd * w[c] + b[c]);
    }
}

// ---------------- build tok (200,206,768) half ----------------
__global__ void gather_tok(const __half* __restrict__ xn, __half* __restrict__ tok)
{
    size_t idx = (size_t)blockIdx.x * 256 + threadIdx.x;
    if (idx >= (size_t)BW * LW * C_) return;
    int c = (int)(idx % C_);
    int rest = (int)(idx / C_);
    int l = rest % LW;
    int bw = rest / LW;
    __half val = __float2half(0.f);
    if (l < VPT) {
        int b = bw & 7;
        val = xn[((size_t)b * L_ + l) * C_ + c];
    } else {
        int r = l - VPT;
        int i = r / WS, j = r % WS;
        int b = bw / NWIN, w = bw % NWIN;
        int h  = (w / 5) * WS + i;
        int wc = (w % 5) * WS + j;
        if (h < 64 && wc < 64)
            val = xn[((size_t)b * L_ + VPT + h * 64 + wc) * C_ + c];
    }
    tok[idx] = val;
}

// ---------------- fp16 GEMM 128x128 tile, 8 warps, warp 64x32, KTILE=64 ----------------
__device__ __forceinline__ float gelu_f(float v) {
    return 0.5f * v * (1.0f + erff(v * 0.70710678118654752f));
}

#define GW 36
#define MATW (128 * GW)
#define STGW (2 * MATW)
#define GEMM_SMEM (3 * STGW * 4)       // 110592 bytes

__device__ __forceinline__ void copy_stage(const __half* __restrict__ A,
        const __half* __restrict__ Bm, int t, int m0, int n0, int M, int K,
        unsigned sbase, int ks)
{
    unsigned sa = sbase + (unsigned)(ks % 3) * (STGW * 4);
    unsigned sb = sa + MATW * 4;
    int kb = ks * 64;
    #pragma unroll
    for (int i = 0; i < 4; i++) {
        int id = t + i * 256;
        int row = id >> 3, ch = id & 7;
        bool av = (m0 + row) < M;
        const __half* src = A + (size_t)(av ? m0 + row : 0) * K + kb + ch * 8;
        CPA16(sa + (row * GW + ch * 4) * 4, src, av);
    }
    #pragma unroll
    for (int i = 0; i < 4; i++) {
        int id = t + i * 256;
        int row = id >> 3, ch = id & 7;
        const __half* src = Bm + (size_t)(n0 + row) * K + kb + ch * 8;
        CPA16(sb + (row * GW + ch * 4) * 4, src, true);
    }
}

template<int MODE, int OUTH>
__global__ void __launch_bounds__(256) gemm_f16(const __half* __restrict__ A,
        const __half* __restrict__ Bm, const float* __restrict__ bias,
        const float* __restrict__ res, void* __restrict__ Cm,
        int M, int N, int K)
{
    extern __shared__ __align__(16) unsigned smp[];
    const int t = threadIdx.x;
    const int m0 = blockIdx.y * 128, n0 = blockIdx.x * 128;
    const int warp = t >> 5, lane = t & 31;
    const int wm = warp >> 2, wn = warp & 3;
    const int g = lane >> 2, c = lane & 3;

    const int rA  = (lane & 7) + ((lane >> 3) & 1) * 8;
    const int kaA = ((lane >> 4) & 1) * 4;
    const int rB  = lane & 7;
    const int kaB = ((lane >> 3) & 1) * 4;

    float acc[4][4][4];
    #pragma unroll
    for (int i = 0; i < 4; i++)
        #pragma unroll
        for (int j = 0; j < 4; j++)
            #pragma unroll
            for (int q = 0; q < 4; q++) acc[i][j][q] = 0.f;

    const unsigned sbase = (unsigned)__cvta_generic_to_shared(smp);

    const int NIT = K >> 6;
    copy_stage(A, Bm, t, m0, n0, M, K, sbase, 0); CP_COMMIT();
    copy_stage(A, Bm, t, m0, n0, M, K, sbase, 1); CP_COMMIT();

    for (int it = 0; it < NIT; it++) {
        asm volatile("cp.async.wait_group 1;");
        __syncthreads();
        unsigned sa = sbase + (unsigned)(it % 3) * (STGW * 4);
        unsigned sb = sa + MATW * 4;
        #pragma unroll
        for (int ks4 = 0; ks4 < 4; ks4++) {
            int ksw = ks4 * 8;
            unsigned af[4][4], bf[4][2];
            #pragma unroll
            for (int mt = 0; mt < 4; mt++) {
                unsigned ad = sa + (((wm * 64 + mt * 16 + rA) * GW) + ksw + kaA) * 4;
                LDM_X4(af[mt][0], af[mt][1], af[mt][2], af[mt][3], ad);
            }
            #pragma unroll
            for (int nt = 0; nt < 4; nt++) {
                unsigned bd = sb + (((wn * 32 + nt * 8 + rB) * GW) + ksw + kaB) * 4;
                asm volatile("ldmatrix.sync.aligned.m8n8.x2.shared.b16 {%0,%1},[%2];"
                    : "=r"(bf[nt][0]), "=r"(bf[nt][1]) : "r"(bd));
            }
            #pragma unroll
            for (int mt = 0; mt < 4; mt++)
                #pragma unroll
                for (int nt = 0; nt < 4; nt++)
                    MMA_F16(acc[mt][nt], af[mt], bf[nt]);
        }
        if (it + 2 < NIT)
            copy_stage(A, Bm, t, m0, n0, M, K, sbase, it + 2);
        CP_COMMIT();
    }

    #pragma unroll
    for (int mt = 0; mt < 4; mt++) {
        #pragma unroll
        for (int hf = 0; hf < 2; hf++) {
            int r = m0 + wm * 64 + mt * 16 + g + hf * 8;
            if (r >= M) continue;
            #pragma unroll
            for (int nt = 0; nt < 4; nt++) {
                int col = n0 + wn * 32 + nt * 8 + 2 * c;
                float v0 = acc[mt][nt][hf * 2 + 0] + bias[col];
                float v1 = acc[mt][nt][hf * 2 + 1] + bias[col + 1];
                if (MODE == 1) { v0 = gelu_f(v0); v1 = gelu_f(v1); }
                if (MODE == 2) {
                    v0 += res[(size_t)r * N + col];
                    v1 += res[(size_t)r * N + col + 1];
                }
                if (OUTH) {
                    __half2 h = __floats2half2_rn(v0, v1);
                    *(__half2*)&((__half*)Cm)[(size_t)r * N + col] = h;
                } else {
                    *(float2*)&((float*)Cm)[(size_t)r * N + col] = make_float2(v0, v1);
                }
            }
        }
    }
}

// ---------------- qk: attn = (q*0.125) @ k^T + relpos, fp16 mma ----------------
#define QSTR 36

__device__ __forceinline__ unsigned hmul2u(unsigned w, __half2 s) {
    __half2 h = *(__half2*)&w;
    h = __hmul2(h, s);
    return *(unsigned*)&h;
}

__global__ void __launch_bounds__(256) qk_mma(const __half* __restrict__ qkv,
        float* __restrict__ attn, const float* __restrict__ rph,
        const float* __restrict__ rpw)
{
    int bh = blockIdx.z;
    int bw = bh / NH, hh = bh % NH;
    int m0 = blockIdx.y * 128, n0 = blockIdx.x * 128;
    const __half* qb = qkv + (size_t)bw * LW * 2304 + hh * HD;
    const __half* kb_ = qb + 768;
    __shared__ __align__(16) unsigned Qs[128 * QSTR];
    __shared__ __align__(16) unsigned Ks[128 * QSTR];
    __shared__ float srl[128 * 28];
    int t = threadIdx.x;
    int warp = t >> 5, lane = t & 31;
    int wm = warp >> 2, wn = warp & 3;
    int g = lane >> 2, c = lane & 3;
    const __half2 sc2 = __float2half2_rn(0.125f);

    float acc[4][4][4];
    #pragma unroll
    for (int i = 0; i < 4; i++)
        #pragma unroll
        for (int j = 0; j < 4; j++)
            #pragma unroll
            for (int q = 0; q < 4; q++) acc[i][j][q] = 0.f;

    #pragma unroll
    for (int i = 0; i < 4; i++) {
        int id = t + i * 256;
        int row = id >> 3, wg = (id & 7) * 4;
        uint4 qv = make_uint4(0, 0, 0, 0), kv = qv;
        if (m0 + row < LW) qv = *(const uint4*)(qb + (size_t)(m0 + row) * 2304 + wg * 2);
        if (n0 + row < LW) kv = *(const uint4*)(kb_ + (size_t)(n0 + row) * 2304 + wg * 2);
        unsigned* qd = &Qs[row * QSTR + wg];
        qd[0] = hmul2u(qv.x, sc2); qd[1] = hmul2u(qv.y, sc2);
        qd[2] = hmul2u(qv.z, sc2); qd[3] = hmul2u(qv.w, sc2);
        unsigned* kd = &Ks[row * QSTR + wg];
        kd[0] = kv.x; kd[1] = kv.y; kd[2] = kv.z; kd[3] = kv.w;
    }
    __syncthreads();

    // rel-pos table: 128 rows x 28 entries; q is scaled by 1/8 (exact) -> x8
    #pragma unroll
    for (int j = 0; j < 14; j++) {
        int task = t + j * 256;
        int row = task / 28, p = task % 28;
        int rowg = m0 + row;
        float s = 0.f;
        if (rowg >= VPT && rowg < LW) {
            int rr = rowg - VPT;
            int qi = rr / WS, qj = rr % WS;
            int dir = p / 14, kk = p % 14;
            const float* rp = dir ? (rpw + (qj - kk + 13) * HD)
                                  : (rph + (qi - kk + 13) * HD);
            const unsigned* qrow = &Qs[row * QSTR];
            #pragma unroll
            for (int w = 0; w < 32; w++) {
                float2 f = __half22float2(*(const __half2*)&qrow[w]);
                s += f.x * rp[2 * w] + f.y * rp[2 * w + 1];
            }
            s *= 8.f;
        }
        srl[row * 28 + p] = s;
    }

    #pragma unroll
    for (int ks = 0; ks < 32; ks += 8) {
        unsigned af[4][4], bf[4][2];
        #pragma unroll
        for (int mt = 0; mt < 4; mt++) {
            int base = (wm * 64 + mt * 16 + g) * QSTR + ks + c;
            af[mt][0] = Qs[base];
            af[mt][1] = Qs[base + 8 * QSTR];
            af[mt][2] = Qs[base + 4];
            af[mt][3] = Qs[base + 8 * QSTR + 4];
        }
        #pragma unroll
        for (int nt = 0; nt < 4; nt++) {
            int base = (wn * 32 + nt * 8 + g) * QSTR + ks + c;
            bf[nt][0] = Ks[base];
            bf[nt][1] = Ks[base + 4];
        }
        #pragma unroll
        for (int mt = 0; mt < 4; mt++)
            #pragma unroll
            for (int nt = 0; nt < 4; nt++)
                MMA_F16(acc[mt][nt], af[mt], bf[nt]);
    }
    __syncthreads();   // srl visible to all epilogue readers

    float* ao = attn + (size_t)bh * ASLAB;
    #pragma unroll
    for (int mt = 0; mt < 4; mt++) {
        #pragma unroll
        for (int hf = 0; hf < 2; hf++) {
            int rloc = wm * 64 + mt * 16 + g + hf * 8;
            int r = m0 + rloc;
            if (r >= LW) continue;
            bool dorel = r >= VPT;
            const float* sr = &srl[rloc * 28];
            #pragma unroll
            for (int nt = 0; nt < 4; nt++) {
                int col = n0 + wn * 32 + nt * 8 + 2 * c;
                if (col >= APITCH) continue;
                float v0 = acc[mt][nt][hf * 2 + 0];
                float v1 = acc[mt][nt][hf * 2 + 1];
                if (dorel) {
                    if (col >= VPT && col < LW) {
                        int cc = col - VPT;
                        v0 += sr[cc / 14] + sr[14 + cc % 14];
                    }
                    if (col + 1 >= VPT && col + 1 < LW) {
                        int cc = col + 1 - VPT;
                        v1 += sr[cc / 14] + sr[14 + cc % 14];
                    }
                }
                *(float2*)&ao[(size_t)r * APITCH + col] = make_float2(v0, v1);
            }
        }
    }
}

// ---------------- streaming softmax (warp per row) -> half P ----------------
__global__ void __launch_bounds__(256) softmax_stream(const float* __restrict__ attn,
        __half* __restrict__ P)
{
    int gid = blockIdx.x * 8 + (threadIdx.x >> 5);
    int lane = threadIdx.x & 31;
    int bh = gid / LW, r = gid % LW;
    const float* arow = attn + (size_t)bh * ASLAB + (size_t)r * APITCH;
    __half* prow = P + (size_t)bh * ASLAB + (size_t)r * APITCH;

    float v[7];
    float mx = -1e30f;
    #pragma unroll
    for (int i = 0; i < 7; i++) {
        int col = lane + 32 * i;
        float val = (col < LW) ? arow[col] : -1e30f;
        v[i] = val;
        mx = fmaxf(mx, val);
    }
    #pragma unroll
    for (int o = 16; o > 0; o >>= 1) mx = fmaxf(mx, __shfl_xor_sync(0xffffffffu, mx, o));
    float sum = 0.f;
    #pragma unroll
    for (int i = 0; i < 7; i++) { v[i] = __expf(v[i] - mx); sum += v[i]; }
    #pragma unroll
    for (int o = 16; o > 0; o >>= 1) sum += __shfl_xor_sync(0xffffffffu, sum, o);
    float inv = 1.f / sum;
    #pragma unroll
    for (int i = 0; i < 7; i++) {
        int col = lane + 32 * i;
        if (col < APITCH) prow[col] = __float2half_rn(v[i] * inv);  // pad cols -> 0
    }
}

// ---------------- av: P(half 128x208) @ V(206x64) -> half, single-sync full tile ----------------
#define PW 108
#define VW 108
#define AV_SMEM ((128 * PW + 64 * VW) * 4)   // 82944 bytes

__global__ void __launch_bounds__(256) av_mma(const __half* __restrict__ P,
        const __half* __restrict__ qkv, __half* __restrict__ av)
{
    int bh = blockIdx.y;
    int m0 = blockIdx.x * 128;
    int bw = bh / NH, hh = bh % NH;
    const __half* vb = qkv + (size_t)bw * LW * 2304 + hh * HD + 1536;
    const __half* pb = P + (size_t)bh * ASLAB;
    extern __shared__ __align__(16) unsigned avs[];
    unsigned* Ps = avs;
    unsigned* Vs = avs + 128 * PW;
    __half* VsH = (__half*)Vs;
    int t = threadIdx.x;
    int warp = t >> 5, lane = t & 31;
    int wm = warp >> 2, wn = warp & 3;
    int g = lane >> 2, c = lane & 3;

    const unsigned sbase = (unsigned)__cvta_generic_to_shared(Ps);
    #pragma unroll
    for (int j = 0; j < 13; j++) {
        int id = t + j * 256;
        int row = id / 26, ch = id % 26;
        bool ok = (m0 + row) < LW;
        const __half* src = pb + (size_t)(ok ? m0 + row : 0) * APITCH + ch * 8;
        CPA16(sbase + (row * PW + ch * 4) * 4, src, ok);
    }
    CP_COMMIT();

    #pragma unroll
    for (int j = 0; j < 13; j++) {
        int id = t + j * 256;
        int l = id >> 4, nc = (id & 15) * 4;
        __half h0 = __float2half(0.f), h1 = h0, h2 = h0, h3 = h0;
        if (l < LW) {
            const __half* vr = vb + (size_t)l * 2304 + nc;
            h0 = vr[0]; h1 = vr[1]; h2 = vr[2]; h3 = vr[3];
        }
        VsH[(nc + 0) * (2 * VW) + l] = h0;
        VsH[(nc + 1) * (2 * VW) + l] = h1;
        VsH[(nc + 2) * (2 * VW) + l] = h2;
        VsH[(nc + 3) * (2 * VW) + l] = h3;
    }
    asm volatile("cp.async.wait_group 0;");
    __syncthreads();

    float acc[4][2][4];
    #pragma unroll
    for (int i = 0; i < 4; i++)
        #pragma unroll
        for (int j = 0; j < 2; j++)
            #pragma unroll
            for (int q = 0; q < 4; q++) acc[i][j][q] = 0.f;

    #pragma unroll
    for (int ks = 0; ks < 104; ks += 8) {
        unsigned af[4][4], bf[2][2];
        #pragma unroll
        for (int mt = 0; mt < 4; mt++) {
            int base = (wm * 64 + mt * 16 + g) * PW + ks + c;
            af[mt][0] = Ps[base];
            af[mt][1] = Ps[base + 8 * PW];
            af[mt][2] = Ps[base + 4];
            af[mt][3] = Ps[base + 8 * PW + 4];
        }
        #pragma unroll
        for (int nt = 0; nt < 2; nt++) {
            int base = (wn * 16 + nt * 8 + g) * VW + ks + c;
            bf[nt][0] = Vs[base];
            bf[nt][1] = Vs[base + 4];
        }
        #pragma unroll
        for (int mt = 0; mt < 4; mt++)
            #pragma unroll
            for (int nt = 0; nt < 2; nt++)
                MMA_F16(acc[mt][nt], af[mt], bf[nt]);
    }

    #pragma unroll
    for (int mt = 0; mt < 4; mt++) {
        #pragma unroll
        for (int hf = 0; hf < 2; hf++) {
            int m = m0 + wm * 64 + mt * 16 + g + hf * 8;
            if (m >= LW) continue;
            __half* o = av + ((size_t)bw * LW + m) * C_ + hh * HD;
            #pragma unroll
            for (int nt = 0; nt < 2; nt++) {
                int col = wn * 16 + nt * 8 + 2 * c;
                __half2 h = __floats2half2_rn(acc[mt][nt][hf * 2], acc[mt][nt][hf * 2 + 1]);
                *(__half2*)&o[col] = h;
            }
        }
    }
}

// ---------------- launch ----------------
extern "C" void kernel_launch(void* const* d_in, const int* in_sizes, int n_in,
                              void* d_out, int out_size)
{
    const float* x      = (const float*)d_in[0];
    const float* ln1_w  = (const float*)d_in[1];
    const float* ln1_b  = (const float*)d_in[2];
    const float* qkv_w  = (const float*)d_in[3];
    const float* qkv_b  = (const float*)d_in[4];
    const float* proj_w = (const float*)d_in[5];
    const float* proj_b = (const float*)d_in[6];
    const float* rph    = (const float*)d_in[7];
    const float* rpw    = (const float*)d_in[8];
    const float* ln2_w  = (const float*)d_in[9];
    const float* ln2_b  = (const float*)d_in[10];
    const float* mlp_w1 = (const float*)d_in[11];
    const float* mlp_b1 = (const float*)d_in[12];
    const float* mlp_w2 = (const float*)d_in[13];
    const float* mlp_b2 = (const float*)d_in[14];
    float* out = (float*)d_out;

    void *xnp, *tokp, *qkvp, *attnp, *projp, *x2p, *wp, *pp;
    cudaGetSymbolAddress(&xnp,   g_xn);
    cudaGetSymbolAddress(&tokp,  g_tok);
    cudaGetSymbolAddress(&qkvp,  g_qkv);
    cudaGetSymbolAddress(&attnp, g_attn);
    cudaGetSymbolAddress(&projp, g_proj);
    cudaGetSymbolAddress(&x2p,   g_x2);
    cudaGetSymbolAddress(&wp,    g_w);
    cudaGetSymbolAddress(&pp,    g_p);

    __half* xn   = (__half*)xnp;
    __half* tok  = (__half*)tokp;
    __half* qkv  = (__half*)qkvp;
    float*  attn = (float*)attnp;
    __half* hid  = (__half*)attnp;
    float*  proj = (float*)projp;
    float*  x2   = (float*)x2p;
    __half* wh   = (__half*)wp;
    __half* P    = (__half*)pp;

    cudaFuncSetAttribute(gemm_f16<0,1>, cudaFuncAttributeMaxDynamicSharedMemorySize, GEMM_SMEM);
    cudaFuncSetAttribute(gemm_f16<0,0>, cudaFuncAttributeMaxDynamicSharedMemorySize, GEMM_SMEM);
    cudaFuncSetAttribute(gemm_f16<1,1>, cudaFuncAttributeMaxDynamicSharedMemorySize, GEMM_SMEM);
    cudaFuncSetAttribute(gemm_f16<2,0>, cudaFuncAttributeMaxDynamicSharedMemorySize, GEMM_SMEM);
    cudaFuncSetAttribute(av_mma,        cudaFuncAttributeMaxDynamicSharedMemorySize, AV_SMEM);

    // 0) convert all weights to fp16 (single launch)
    convert_w_all<<<(N_WTOT + 255) / 256, 256>>>(qkv_w, proj_w, mlp_w1, mlp_w2, wh);

    // 1) LN1 -> half
    ln_kernel<<<MX, 256>>>(x, ln1_w, ln1_b, xn);
    // 2) tok gather (half)
    gather_tok<<<(int)(((size_t)BW * LW * C_ + 255) / 256), 256>>>(xn, tok);
    // 3) qkv = tok @ qkv_w^T + b -> half
    gemm_f16<0,1><<<dim3(2304 / 128, (MQ + 127) / 128), 256, GEMM_SMEM>>>(
        tok, wh + WOFF_QKV, qkv_b, nullptr, qkv, MQ, 2304, 768);
    // 4) attn = q*scale @ k^T + relpos -> fp32
    qk_mma<<<dim3(2, 2, BH), 256>>>(qkv, attn, rph, rpw);
    // 5) streaming softmax -> half P
    softmax_stream<<<BH * LW / 8, 256>>>(attn, P);
    // 6) P @ v -> half av (single-sync full-tile)
    av_mma<<<dim3(2, BH), 256, AV_SMEM>>>(P, qkv, tok);
    // 7) proj -> fp32
    gemm_f16<0,0><<<dim3(768 / 128, (MQ + 127) / 128), 256, GEMM_SMEM>>>(
        tok, wh + WOFF_PROJ, proj_b, nullptr, proj, MQ, 768, 768);
    // 8+9) combine + residual + LN2 fused
    combine_ln<<<MX, 256>>>(x, proj, ln2_w, ln2_b, x2, xn);
    // 10) MLP fc1 + gelu -> half hidden
    gemm_f16<1,1><<<dim3(3072 / 128, (MX + 127) / 128), 256, GEMM_SMEM>>>(
        xn, wh + WOFF_W1, mlp_b1, nullptr, hid, MX, 3072, 768);
    // 11) MLP fc2 + residual -> fp32 out
    gemm_f16<2,0><<<dim3(768 / 128, (MX + 127) / 128), 256, GEMM_SMEM>>>(
        hid, wh + WOFF_W2, mlp_b2, x2, out, MX, 768, 3072);
}

// round 15
// speedup vs baseline: 2.6127x; 2.6127x over previous
#include <cuda_runtime.h>
#include <cuda_fp16.h>
#include <math.h>

#define B_    8
#define L_    4106
#define C_    768
#define VPT   10
#define NH    12
#define HD    64
#define WS    14
#define NWIN  25
#define BW    200
#define LW    206
#define BH    2400
#define MX    32848        // B_*L_
#define MQ    41200        // BW*LW
#define APITCH 208
#define ASLAB  (APITCH*APITCH)

// ---------------- scratch (static, allocation-free) ----------------
__device__ float  g_xn [25227264];    // half: LN1 out / LN2 out
__device__ float  g_tok[31641600];    // half: tok; later attn@v (half)
__device__ float  g_qkv[94924800];    // half: qkv
__device__ float  g_attn[103850000];  // fp32 attn scores; later half MLP hidden
__device__ float  g_proj[31641600];   // rel table (13.8M floats) early; fp32 proj out later
__device__ float  g_x2 [25227264];    // fp32 residual
__device__ float  g_w  [7077888];     // half: converted weights qkv|proj|w1|w2
__device__ __half g_p  [103900000];   // half: softmax P

#define WOFF_QKV  0
#define WOFF_PROJ 1769472
#define WOFF_W1   2359296
#define WOFF_W2   4718592
#define N_WTOT    7077888

#define CPA16(dst_u32, src_ptr, pred) \
    asm volatile("cp.async.cg.shared.global [%0], [%1], 16, %2;" \
                 :: "r"(dst_u32), "l"(src_ptr), "r"((pred) ? 16 : 0))
#define CP_COMMIT() asm volatile("cp.async.commit_group;")

#define MMA_F16(d, a, b) \
    asm volatile("mma.sync.aligned.m16n8k16.row.col.f32.f16.f16.f32 " \
        "{%0,%1,%2,%3},{%4,%5,%6,%7},{%8,%9},{%0,%1,%2,%3};" \
        : "+f"(d[0]), "+f"(d[1]), "+f"(d[2]), "+f"(d[3]) \
        : "r"(a[0]), "r"(a[1]), "r"(a[2]), "r"(a[3]), "r"(b[0]), "r"(b[1]))

#define LDM_X4(r0, r1, r2, r3, addr) \
    asm volatile("ldmatrix.sync.aligned.m8n8.x4.shared.b16 {%0,%1,%2,%3},[%4];" \
        : "=r"(r0), "=r"(r1), "=r"(r2), "=r"(r3) : "r"(addr))

// ---------------- all-weights convert fp32 -> fp16 (single launch) ----------------
__global__ void convert_w_all(const float* __restrict__ qkv_w,
        const float* __restrict__ proj_w, const float* __restrict__ w1,
        const float* __restrict__ w2, __half* __restrict__ out)
{
    int i = blockIdx.x * 256 + threadIdx.x;
    if (i >= N_WTOT) return;
    float v;
    if (i < WOFF_PROJ)      v = qkv_w[i];
    else if (i < WOFF_W1)   v = proj_w[i - WOFF_PROJ];
    else if (i < WOFF_W2)   v = w1[i - WOFF_W1];
    else                    v = w2[i - WOFF_W2];
    out[i] = __float2half_rn(v);
}

// ---------------- LayerNorm, half out ----------------
__global__ void __launch_bounds__(256) ln_kernel(const float* __restrict__ x,
        const float* __restrict__ w, const float* __restrict__ b,
        __half* __restrict__ out)
{
    int row = blockIdx.x, t = threadIdx.x;
    const float* xr = x + (size_t)row * C_;
    float v0 = xr[t], v1 = xr[t + 256], v2 = xr[t + 512];
    float s  = v0 + v1 + v2;
    float s2 = v0 * v0 + v1 * v1 + v2 * v2;
    __shared__ float r1[8], r2[8];
    #pragma unroll
    for (int o = 16; o > 0; o >>= 1) {
        s  += __shfl_xor_sync(0xffffffffu, s,  o);
        s2 += __shfl_xor_sync(0xffffffffu, s2, o);
    }
    if ((t & 31) == 0) { r1[t >> 5] = s; r2[t >> 5] = s2; }
    __syncthreads();
    float S = 0.f, S2 = 0.f;
    #pragma unroll
    for (int wi = 0; wi < 8; wi++) { S += r1[wi]; S2 += r2[wi]; }
    float mean = S * (1.f / C_);
    float var  = S2 * (1.f / C_) - mean * mean;
    float rstd = rsqrtf(var + 1e-5f);
    __half* orow = out + (size_t)row * C_;
    orow[t]       = __float2half_rn((v0 - mean) * rstd * w[t]       + b[t]);
    orow[t + 256] = __float2half_rn((v1 - mean) * rstd * w[t + 256] + b[t + 256]);
    orow[t + 512] = __float2half_rn((v2 - mean) * rstd * w[t + 512] + b[t + 512]);
}

// ---------------- fused un-window + prompt-mean + residual + LN2 ----------------
__global__ void __launch_bounds__(256) combine_ln(const float* __restrict__ x,
        const float* __restrict__ proj, const float* __restrict__ w,
        const float* __restrict__ b, float* __restrict__ x2,
        __half* __restrict__ xn)
{
    int row = blockIdx.x, t = threadIdx.x;
    int bb = row / L_, tt = row % L_;
    const float* psrc = nullptr;
    bool prompt = (tt < VPT);
    if (!prompt) {
        int sp = tt - VPT;
        int h = sp >> 6, wc = sp & 63;
        int wh = h / WS,  i2 = h % WS;
        int ww = wc / WS, j2 = wc % WS;
        int bw = bb * NWIN + wh * 5 + ww;
        int l  = VPT + i2 * WS + j2;
        psrc = proj + ((size_t)bw * LW + l) * C_;
    }
    float v[3];
    #pragma unroll
    for (int j = 0; j < 3; j++) {
        int c = t + j * 256;
        float val;
        if (prompt) {
            float s = 0.f;
            #pragma unroll
            for (int w2 = 0; w2 < NWIN; w2++)
                s += proj[((size_t)(w2 * B_ + bb) * LW + tt) * C_ + c];
            val = s * (1.f / NWIN);
        } else {
            val = psrc[c];
        }
        v[j] = x[(size_t)row * C_ + c] + val;
        x2[(size_t)row * C_ + c] = v[j];
    }
    float s  = v[0] + v[1] + v[2];
    float s2 = v[0] * v[0] + v[1] * v[1] + v[2] * v[2];
    __shared__ float r1[8], r2[8];
    #pragma unroll
    for (int o = 16; o > 0; o >>= 1) {
        s  += __shfl_xor_sync(0xffffffffu, s,  o);
        s2 += __shfl_xor_sync(0xffffffffu, s2, o);
    }
    if ((t & 31) == 0) { r1[t >> 5] = s; r2[t >> 5] = s2; }
    __syncthreads();
    float S = 0.f, S2 = 0.f;
    #pragma unroll
    for (int wi = 0; wi < 8; wi++) { S += r1[wi]; S2 += r2[wi]; }
    float mean = S * (1.f / C_);
    float var  = S2 * (1.f / C_) - mean * mean;
    float rstd = rsqrtf(var + 1e-5f);
    __half* orow = xn + (size_t)row * C_;
    #pragma unroll
    for (int j = 0; j < 3; j++) {
        int c = t + j * 256;
        orow[c] = __float2half_rn((v[j] - mean) * rstd * w[c] + b[c]);
    }
}

// ---------------- build tok (200,206,768) half ----------------
__global__ void gather_tok(const __half* __restrict__ xn, __half* __restrict__ tok)
{
    size_t idx = (size_t)blockIdx.x * 256 + threadIdx.x;
    if (idx >= (size_t)BW * LW * C_) return;
    int c = (int)(idx % C_);
    int rest = (int)(idx / C_);
    int l = rest % LW;
    int bw = rest / LW;
    __half val = __float2half(0.f);
    if (l < VPT) {
        int b = bw & 7;
        val = xn[((size_t)b * L_ + l) * C_ + c];
    } else {
        int r = l - VPT;
        int i = r / WS, j = r % WS;
        int b = bw / NWIN, w = bw % NWIN;
        int h  = (w / 5) * WS + i;
        int wc = (w % 5) * WS + j;
        if (h < 64 && wc < 64)
            val = xn[((size_t)b * L_ + VPT + h * 64 + wc) * C_ + c];
    }
    tok[idx] = val;
}

// ---------------- fp16 GEMM 128x128 tile, 8 warps, warp 64x32, KTILE=64 ----------------
__device__ __forceinline__ float gelu_f(float v) {
    return 0.5f * v * (1.0f + erff(v * 0.70710678118654752f));
}

#define GW 36
#define MATW (128 * GW)
#define STGW (2 * MATW)
#define GEMM_SMEM (3 * STGW * 4)       // 110592 bytes

__device__ __forceinline__ void copy_stage(const __half* __restrict__ A,
        const __half* __restrict__ Bm, int t, int m0, int n0, int M, int K,
        unsigned sbase, int ks)
{
    unsigned sa = sbase + (unsigned)(ks % 3) * (STGW * 4);
    unsigned sb = sa + MATW * 4;
    int kb = ks * 64;
    #pragma unroll
    for (int i = 0; i < 4; i++) {
        int id = t + i * 256;
        int row = id >> 3, ch = id & 7;
        bool av = (m0 + row) < M;
        const __half* src = A + (size_t)(av ? m0 + row : 0) * K + kb + ch * 8;
        CPA16(sa + (row * GW + ch * 4) * 4, src, av);
    }
    #pragma unroll
    for (int i = 0; i < 4; i++) {
        int id = t + i * 256;
        int row = id >> 3, ch = id & 7;
        const __half* src = Bm + (size_t)(n0 + row) * K + kb + ch * 8;
        CPA16(sb + (row * GW + ch * 4) * 4, src, true);
    }
}

template<int MODE, int OUTH>
__global__ void __launch_bounds__(256) gemm_f16(const __half* __restrict__ A,
        const __half* __restrict__ Bm, const float* __restrict__ bias,
        const float* __restrict__ res, void* __restrict__ Cm,
        int M, int N, int K)
{
    extern __shared__ __align__(16) unsigned smp[];
    const int t = threadIdx.x;
    const int m0 = blockIdx.y * 128, n0 = blockIdx.x * 128;
    const int warp = t >> 5, lane = t & 31;
    const int wm = warp >> 2, wn = warp & 3;
    const int g = lane >> 2, c = lane & 3;

    const int rA  = (lane & 7) + ((lane >> 3) & 1) * 8;
    const int kaA = ((lane >> 4) & 1) * 4;
    const int rB  = lane & 7;
    const int kaB = ((lane >> 3) & 1) * 4;

    float acc[4][4][4];
    #pragma unroll
    for (int i = 0; i < 4; i++)
        #pragma unroll
        for (int j = 0; j < 4; j++)
            #pragma unroll
            for (int q = 0; q < 4; q++) acc[i][j][q] = 0.f;

    const unsigned sbase = (unsigned)__cvta_generic_to_shared(smp);

    const int NIT = K >> 6;
    copy_stage(A, Bm, t, m0, n0, M, K, sbase, 0); CP_COMMIT();
    copy_stage(A, Bm, t, m0, n0, M, K, sbase, 1); CP_COMMIT();

    for (int it = 0; it < NIT; it++) {
        asm volatile("cp.async.wait_group 1;");
        __syncthreads();
        unsigned sa = sbase + (unsigned)(it % 3) * (STGW * 4);
        unsigned sb = sa + MATW * 4;
        #pragma unroll
        for (int ks4 = 0; ks4 < 4; ks4++) {
            int ksw = ks4 * 8;
            unsigned af[4][4], bf[4][2];
            #pragma unroll
            for (int mt = 0; mt < 4; mt++) {
                unsigned ad = sa + (((wm * 64 + mt * 16 + rA) * GW) + ksw + kaA) * 4;
                LDM_X4(af[mt][0], af[mt][1], af[mt][2], af[mt][3], ad);
            }
            #pragma unroll
            for (int nt = 0; nt < 4; nt++) {
                unsigned bd = sb + (((wn * 32 + nt * 8 + rB) * GW) + ksw + kaB) * 4;
                asm volatile("ldmatrix.sync.aligned.m8n8.x2.shared.b16 {%0,%1},[%2];"
                    : "=r"(bf[nt][0]), "=r"(bf[nt][1]) : "r"(bd));
            }
            #pragma unroll
            for (int mt = 0; mt < 4; mt++)
                #pragma unroll
                for (int nt = 0; nt < 4; nt++)
                    MMA_F16(acc[mt][nt], af[mt], bf[nt]);
        }
        if (it + 2 < NIT)
            copy_stage(A, Bm, t, m0, n0, M, K, sbase, it + 2);
        CP_COMMIT();
    }

    #pragma unroll
    for (int mt = 0; mt < 4; mt++) {
        #pragma unroll
        for (int hf = 0; hf < 2; hf++) {
            int r = m0 + wm * 64 + mt * 16 + g + hf * 8;
            if (r >= M) continue;
            #pragma unroll
            for (int nt = 0; nt < 4; nt++) {
                int col = n0 + wn * 32 + nt * 8 + 2 * c;
                float v0 = acc[mt][nt][hf * 2 + 0] + bias[col];
                float v1 = acc[mt][nt][hf * 2 + 1] + bias[col + 1];
                if (MODE == 1) { v0 = gelu_f(v0); v1 = gelu_f(v1); }
                if (MODE == 2) {
                    v0 += res[(size_t)r * N + col];
                    v1 += res[(size_t)r * N + col + 1];
                }
                if (OUTH) {
                    __half2 h = __floats2half2_rn(v0, v1);
                    *(__half2*)&((__half*)Cm)[(size_t)r * N + col] = h;
                } else {
                    *(float2*)&((float*)Cm)[(size_t)r * N + col] = make_float2(v0, v1);
                }
            }
        }
    }
}

// ---------------- qk: attn = (q*0.125) @ k^T, fp16 mma ----------------
#define QSTR 36

__device__ __forceinline__ unsigned hmul2u(unsigned w, __half2 s) {
    __half2 h = *(__half2*)&w;
    h = __hmul2(h, s);
    return *(unsigned*)&h;
}

__global__ void __launch_bounds__(256) qk_mma(const __half* __restrict__ qkv,
                                              float* __restrict__ attn)
{
    int bh = blockIdx.z;
    int bw = bh / NH, hh = bh % NH;
    int m0 = blockIdx.y * 128, n0 = blockIdx.x * 128;
    const __half* qb = qkv + (size_t)bw * LW * 2304 + hh * HD;
    const __half* kb_ = qb + 768;
    __shared__ __align__(16) unsigned Qs[128 * QSTR];
    __shared__ __align__(16) unsigned Ks[128 * QSTR];
    int t = threadIdx.x;
    int warp = t >> 5, lane = t & 31;
    int wm = warp >> 2, wn = warp & 3;
    int g = lane >> 2, c = lane & 3;
    const __half2 sc2 = __float2half2_rn(0.125f);

    float acc[4][4][4];
    #pragma unroll
    for (int i = 0; i < 4; i++)
        #pragma unroll
        for (int j = 0; j < 4; j++)
            #pragma unroll
            for (int q = 0; q < 4; q++) acc[i][j][q] = 0.f;

    #pragma unroll
    for (int i = 0; i < 4; i++) {
        int id = t + i * 256;
        int row = id >> 3, wg = (id & 7) * 4;
        uint4 qv = make_uint4(0, 0, 0, 0), kv = qv;
        if (m0 + row < LW) qv = *(const uint4*)(qb + (size_t)(m0 + row) * 2304 + wg * 2);
        if (n0 + row < LW) kv = *(const uint4*)(kb_ + (size_t)(n0 + row) * 2304 + wg * 2);
        unsigned* qd = &Qs[row * QSTR + wg];
        qd[0] = hmul2u(qv.x, sc2); qd[1] = hmul2u(qv.y, sc2);
        qd[2] = hmul2u(qv.z, sc2); qd[3] = hmul2u(qv.w, sc2);
        unsigned* kd = &Ks[row * QSTR + wg];
        kd[0] = kv.x; kd[1] = kv.y; kd[2] = kv.z; kd[3] = kv.w;
    }
    __syncthreads();

    #pragma unroll
    for (int ks = 0; ks < 32; ks += 8) {
        unsigned af[4][4], bf[4][2];
        #pragma unroll
        for (int mt = 0; mt < 4; mt++) {
            int base = (wm * 64 + mt * 16 + g) * QSTR + ks + c;
            af[mt][0] = Qs[base];
            af[mt][1] = Qs[base + 8 * QSTR];
            af[mt][2] = Qs[base + 4];
            af[mt][3] = Qs[base + 8 * QSTR + 4];
        }
        #pragma unroll
        for (int nt = 0; nt < 4; nt++) {
            int base = (wn * 32 + nt * 8 + g) * QSTR + ks + c;
            bf[nt][0] = Ks[base];
            bf[nt][1] = Ks[base + 4];
        }
        #pragma unroll
        for (int mt = 0; mt < 4; mt++)
            #pragma unroll
            for (int nt = 0; nt < 4; nt++)
                MMA_F16(acc[mt][nt], af[mt], bf[nt]);
    }

    float* ao = attn + (size_t)bh * ASLAB;
    #pragma unroll
    for (int mt = 0; mt < 4; mt++) {
        #pragma unroll
        for (int hf = 0; hf < 2; hf++) {
            int r = m0 + wm * 64 + mt * 16 + g + hf * 8;
            if (r >= LW) continue;
            #pragma unroll
            for (int nt = 0; nt < 4; nt++) {
                int col = n0 + wn * 32 + nt * 8 + 2 * c;
                if (col < APITCH)
                    *(float2*)&ao[(size_t)r * APITCH + col] =
                        make_float2(acc[mt][nt][hf * 2], acc[mt][nt][hf * 2 + 1]);
            }
        }
    }
}

// ---------------- rel table: rel[bh][row][28] = q(row) . rp, smem-staged ----------------
__global__ void __launch_bounds__(256) rel_kernel(const __half* __restrict__ qkv,
        float* __restrict__ rel, const float* __restrict__ rph,
        const float* __restrict__ rpw)
{
    int bh = blockIdx.y;
    int m0 = blockIdx.x * 64;
    int bw = bh / NH, hh = bh % NH;
    const __half* qb = qkv + (size_t)bw * LW * 2304 + hh * HD;
    __shared__ float rps[2 * 27 * HD];    // rph then rpw (13824 B)
    __shared__ float qs[64 * HD];         // 64 q rows fp32 (16384 B)
    int t = threadIdx.x;

    #pragma unroll
    for (int i = 0; i < 7; i++) {
        int idx = t + i * 256;
        if (idx < 27 * HD) rps[idx] = rph[idx];
        if (idx < 27 * HD) rps[27 * HD + idx] = rpw[idx];
    }
    #pragma unroll
    for (int i = 0; i < 16; i++) {
        int idx = t + i * 256;            // 4096 elements
        int row = idx >> 6, d = idx & 63;
        float v = 0.f;
        if (m0 + row < LW) v = __half2float(qb[(size_t)(m0 + row) * 2304 + d]);
        qs[idx] = v;
    }
    __syncthreads();

    #pragma unroll
    for (int j = 0; j < 7; j++) {
        int task = t + j * 256;           // 1792 tasks
        int row = task / 28, p = task % 28;
        int rowg = m0 + row;
        float s = 0.f;
        if (rowg >= VPT && rowg < LW) {
            int rr = rowg - VPT;
            int qi = rr / WS, qj = rr % WS;
            int dir = p / 14, kk = p % 14;
            const float* rp = dir ? &rps[27 * HD + (qj - kk + 13) * HD]
                                  : &rps[(qi - kk + 13) * HD];
            const float* qr = &qs[row * HD];
            #pragma unroll
            for (int d = 0; d < HD; d++) s += qr[d] * rp[d];
        }
        if (rowg < LW) rel[((size_t)bh * LW + rowg) * 28 + p] = s;
    }
}

// ---------------- streaming softmax (warp per row) + rel add -> half P ----------------
__global__ void __launch_bounds__(256) softmax_stream(const float* __restrict__ attn,
        const float* __restrict__ rel, __half* __restrict__ P)
{
    int gid = blockIdx.x * 8 + (threadIdx.x >> 5);
    int lane = threadIdx.x & 31;
    int bh = gid / LW, r = gid % LW;
    const float* arow = attn + (size_t)bh * ASLAB + (size_t)r * APITCH;
    __half* prow = P + (size_t)bh * ASLAB + (size_t)r * APITCH;
    bool dorel = (r >= VPT);

    float srel = 0.f;
    if (dorel && lane < 28)
        srel = rel[((size_t)bh * LW + r) * 28 + lane];

    float v[7];
    float mx = -1e30f;
    #pragma unroll
    for (int i = 0; i < 7; i++) {
        int col = lane + 32 * i;
        float val = (col < LW) ? arow[col] : -1e30f;
        int cc = col - VPT; if (cc < 0) cc = 0;
        float sh = __shfl_sync(0xffffffffu, srel, cc / 14);
        float sw = __shfl_sync(0xffffffffu, srel, 14 + cc % 14);
        if (dorel && col >= VPT && col < LW) val += sh + sw;
        v[i] = val;
        mx = fmaxf(mx, val);
    }
    #pragma unroll
    for (int o = 16; o > 0; o >>= 1) mx = fmaxf(mx, __shfl_xor_sync(0xffffffffu, mx, o));
    float sum = 0.f;
    #pragma unroll
    for (int i = 0; i < 7; i++) { v[i] = __expf(v[i] - mx); sum += v[i]; }
    #pragma unroll
    for (int o = 16; o > 0; o >>= 1) sum += __shfl_xor_sync(0xffffffffu, sum, o);
    float inv = 1.f / sum;
    #pragma unroll
    for (int i = 0; i < 7; i++) {
        int col = lane + 32 * i;
        if (col < APITCH) prow[col] = __float2half_rn(v[i] * inv);
    }
}

// ---------------- av: P(half 128x208) @ V(206x64) -> half, single-sync full tile ----------------
#define PW 108
#define VW 108
#define AV_SMEM ((128 * PW + 64 * VW) * 4)   // 82944 bytes

__global__ void __launch_bounds__(256) av_mma(const __half* __restrict__ P,
        const __half* __restrict__ qkv, __half* __restrict__ av)
{
    int bh = blockIdx.y;
    int m0 = blockIdx.x * 128;
    int bw = bh / NH, hh = bh % NH;
    const __half* vb = qkv + (size_t)bw * LW * 2304 + hh * HD + 1536;
    const __half* pb = P + (size_t)bh * ASLAB;
    extern __shared__ __align__(16) unsigned avs[];
    unsigned* Ps = avs;
    unsigned* Vs = avs + 128 * PW;
    __half* VsH = (__half*)Vs;
    int t = threadIdx.x;
    int warp = t >> 5, lane = t & 31;
    int wm = warp >> 2, wn = warp & 3;
    int g = lane >> 2, c = lane & 3;

    const unsigned sbase = (unsigned)__cvta_generic_to_shared(Ps);
    #pragma unroll
    for (int j = 0; j < 13; j++) {
        int id = t + j * 256;
        int row = id / 26, ch = id % 26;
        bool ok = (m0 + row) < LW;
        const __half* src = pb + (size_t)(ok ? m0 + row : 0) * APITCH + ch * 8;
        CPA16(sbase + (row * PW + ch * 4) * 4, src, ok);
    }
    CP_COMMIT();

    #pragma unroll
    for (int j = 0; j < 13; j++) {
        int id = t + j * 256;
        int l = id >> 4, nc = (id & 15) * 4;
        __half h0 = __float2half(0.f), h1 = h0, h2 = h0, h3 = h0;
        if (l < LW) {
            const __half* vr = vb + (size_t)l * 2304 + nc;
            h0 = vr[0]; h1 = vr[1]; h2 = vr[2]; h3 = vr[3];
        }
        VsH[(nc + 0) * (2 * VW) + l] = h0;
        VsH[(nc + 1) * (2 * VW) + l] = h1;
        VsH[(nc + 2) * (2 * VW) + l] = h2;
        VsH[(nc + 3) * (2 * VW) + l] = h3;
    }
    asm volatile("cp.async.wait_group 0;");
    __syncthreads();

    float acc[4][2][4];
    #pragma unroll
    for (int i = 0; i < 4; i++)
        #pragma unroll
        for (int j = 0; j < 2; j++)
            #pragma unroll
            for (int q = 0; q < 4; q++) acc[i][j][q] = 0.f;

    #pragma unroll
    for (int ks = 0; ks < 104; ks += 8) {
        unsigned af[4][4], bf[2][2];
        #pragma unroll
        for (int mt = 0; mt < 4; mt++) {
            int base = (wm * 64 + mt * 16 + g) * PW + ks + c;
            af[mt][0] = Ps[base];
            af[mt][1] = Ps[base + 8 * PW];
            af[mt][2] = Ps[base + 4];
            af[mt][3] = Ps[base + 8 * PW + 4];
        }
        #pragma unroll
        for (int nt = 0; nt < 2; nt++) {
            int base = (wn * 16 + nt * 8 + g) * VW + ks + c;
            bf[nt][0] = Vs[base];
            bf[nt][1] = Vs[base + 4];
        }
        #pragma unroll
        for (int mt = 0; mt < 4; mt++)
            #pragma unroll
            for (int nt = 0; nt < 2; nt++)
                MMA_F16(acc[mt][nt], af[mt], bf[nt]);
    }

    #pragma unroll
    for (int mt = 0; mt < 4; mt++) {
        #pragma unroll
        for (int hf = 0; hf < 2; hf++) {
            int m = m0 + wm * 64 + mt * 16 + g + hf * 8;
            if (m >= LW) continue;
            __half* o = av + ((size_t)bw * LW + m) * C_ + hh * HD;
            #pragma unroll
            for (int nt = 0; nt < 2; nt++) {
                int col = wn * 16 + nt * 8 + 2 * c;
                __half2 h = __floats2half2_rn(acc[mt][nt][hf * 2], acc[mt][nt][hf * 2 + 1]);
                *(__half2*)&o[col] = h;
            }
        }
    }
}

// ---------------- launch ----------------
extern "C" void kernel_launch(void* const* d_in, const int* in_sizes, int n_in,
                              void* d_out, int out_size)
{
    const float* x      = (const float*)d_in[0];
    const float* ln1_w  = (const float*)d_in[1];
    const float* ln1_b  = (const float*)d_in[2];
    const float* qkv_w  = (const float*)d_in[3];
    const float* qkv_b  = (const float*)d_in[4];
    const float* proj_w = (const float*)d_in[5];
    const float* proj_b = (const float*)d_in[6];
    const float* rph    = (const float*)d_in[7];
    const float* rpw    = (const float*)d_in[8];
    const float* ln2_w  = (const float*)d_in[9];
    const float* ln2_b  = (const float*)d_in[10];
    const float* mlp_w1 = (const float*)d_in[11];
    const float* mlp_b1 = (const float*)d_in[12];
    const float* mlp_w2 = (const float*)d_in[13];
    const float* mlp_b2 = (const float*)d_in[14];
    float* out = (float*)d_out;

    void *xnp, *tokp, *qkvp, *attnp, *projp, *x2p, *wp, *pp;
    cudaGetSymbolAddress(&xnp,   g_xn);
    cudaGetSymbolAddress(&tokp,  g_tok);
    cudaGetSymbolAddress(&qkvp,  g_qkv);
    cudaGetSymbolAddress(&attnp, g_attn);
    cudaGetSymbolAddress(&projp, g_proj);
    cudaGetSymbolAddress(&x2p,   g_x2);
    cudaGetSymbolAddress(&wp,    g_w);
    cudaGetSymbolAddress(&pp,    g_p);

    __half* xn   = (__half*)xnp;
    __half* tok  = (__half*)tokp;
    __half* qkv  = (__half*)qkvp;
    float*  attn = (float*)attnp;
    __half* hid  = (__half*)attnp;
    float*  proj = (float*)projp;
    float*  rel  = (float*)projp;       // rel table lives in proj buffer (used before proj)
    float*  x2   = (float*)x2p;
    __half* wh   = (__half*)wp;
    __half* P    = (__half*)pp;

    cudaFuncSetAttribute(gemm_f16<0,1>, cudaFuncAttributeMaxDynamicSharedMemorySize, GEMM_SMEM);
    cudaFuncSetAttribute(gemm_f16<0,0>, cudaFuncAttributeMaxDynamicSharedMemorySize, GEMM_SMEM);
    cudaFuncSetAttribute(gemm_f16<1,1>, cudaFuncAttributeMaxDynamicSharedMemorySize, GEMM_SMEM);
    cudaFuncSetAttribute(gemm_f16<2,0>, cudaFuncAttributeMaxDynamicSharedMemorySize, GEMM_SMEM);
    cudaFuncSetAttribute(av_mma,        cudaFuncAttributeMaxDynamicSharedMemorySize, AV_SMEM);

    // 0) convert all weights to fp16 (single launch)
    convert_w_all<<<(N_WTOT + 255) / 256, 256>>>(qkv_w, proj_w, mlp_w1, mlp_w2, wh);

    // 1) LN1 -> half
    ln_kernel<<<MX, 256>>>(x, ln1_w, ln1_b, xn);
    // 2) tok gather (half)
    gather_tok<<<(int)(((size_t)BW * LW * C_ + 255) / 256), 256>>>(xn, tok);
    // 3) qkv = tok @ qkv_w^T + b -> half
    gemm_f16<0,1><<<dim3(2304 / 128, (MQ + 127) / 128), 256, GEMM_SMEM>>>(
        tok, wh + WOFF_QKV, qkv_b, nullptr, qkv, MQ, 2304, 768);
    // 4) attn = q*scale @ k^T -> fp32
    qk_mma<<<dim3(2, 2, BH), 256>>>(qkv, attn);
    // 4b) rel table (smem-staged; uses proj buffer as scratch)
    rel_kernel<<<dim3(4, BH), 256>>>(qkv, rel, rph, rpw);
    // 5) streaming softmax + rel -> half P
    softmax_stream<<<BH * LW / 8, 256>>>(attn, rel, P);
    // 6) P @ v -> half av (single-sync full-tile)
    av_mma<<<dim3(2, BH), 256, AV_SMEM>>>(P, qkv, tok);
    // 7) proj -> fp32 (overwrites rel scratch)
    gemm_f16<0,0><<<dim3(768 / 128, (MQ + 127) / 128), 256, GEMM_SMEM>>>(
        tok, wh + WOFF_PROJ, proj_b, nullptr, proj, MQ, 768, 768);
    // 8+9) combine + residual + LN2 fused
    combine_ln<<<MX, 256>>>(x, proj, ln2_w, ln2_b, x2, xn);
    // 10) MLP fc1 + gelu -> half hidden
    gemm_f16<1,1><<<dim3(3072 / 128, (MX + 127) / 128), 256, GEMM_SMEM>>>(
        xn, wh + WOFF_W1, mlp_b1, nullptr, hid, MX, 3072, 768);
    // 11) MLP fc2 + residual -> fp32 out
    gemm_f16<2,0><<<dim3(768 / 128, (MX + 127) / 128), 256, GEMM_SMEM>>>(
        hid, wh + WOFF_W2, mlp_b2, x2, out, MX, 768, 3072);
}